// round 8
// baseline (speedup 1.0000x reference)
#include <cuda_runtime.h>

// NashCascadeNetwork: 8 layers x 524288 buckets, 8 spigots/bucket.
// Inputs (metadata order): H[NB] f32, S[NB,8,2] f32, theta[NB*8] f32, precip[1] f32
// Output (f32): [ H_new(NB) | s_q(NB*8) | network_outflow(1) ]
//
// Persistent-chunk design: grid = 148*8 blocks (one wave), each block owns a
// contiguous range of 128-bucket chunks and carries the chain outflow across
// iterations in smem, so the bucket[b-1] coupling costs nothing.

#define NB          4194304
#define NS          8
#define BPL         524288                   // buckets in last layer
#define CHUNK       128                      // buckets per loop iteration
#define NTHREADS    256                      // 4 threads per bucket, 2 buckets/quad
#define NCHUNKS     (NB / CHUNK)             // 32768
#define GRID        1184                     // 148 SMs * 8 blocks
#define CH_BASE     (NCHUNKS / GRID)         // 27
#define CH_REM      (NCHUNKS - CH_BASE*GRID) // 800 blocks get one extra chunk
#define FIRST_LAST_CHUNK ((NB - BPL) / CHUNK) // 28672
#define OUT_SQ_OFF  NB
#define OUT_SCALAR  (NB * (NS + 1))          // 37748736

__device__ double   g_partials[GRID];
__device__ unsigned g_count = 0;

// q = theta * sqrt(2*9.8*h) * 0.5*(tanh(h)+1) * area,  h = max(0, H - height)
// 0.5*(tanh(h)+1) == sigmoid(2h) == 1/(1+exp(-2h))  -> EX2 + RCP (err ~1e-7)
__device__ __forceinline__ float spigot_q(float Hb, float sh, float sa, float th) {
    float h = fmaxf(0.0f, Hb - sh);
    float e = __expf(-2.0f * h);
    float mod;
    asm("rcp.approx.f32 %0, %1;" : "=f"(mod) : "f"(1.0f + e));
    float s;
    asm("sqrt.approx.f32 %0, %1;" : "=f"(s) : "f"(19.6f * h));
    return th * s * mod * sa;
}

__global__ __launch_bounds__(NTHREADS, 8)
void nash_main(const float* __restrict__ H,
               const float4* __restrict__ S4,     // [NB*4] : (h0,a0,h1,a1) per quad-lane
               const float2* __restrict__ T2,     // [NB*4]
               const float* __restrict__ precip,
               float* __restrict__ out)
{
    float*  Hn  = out;
    float2* SQ2 = (float2*)(out + OUT_SQ_OFF);

    const int tid  = threadIdx.x;
    const int quad = tid >> 2;               // 0..63
    const int ql   = tid & 3;                // 2 spigots per lane

    const int bid  = blockIdx.x;
    const int cbeg = bid * CH_BASE + min(bid, CH_REM);
    const int cend = cbeg + CH_BASE + (bid < CH_REM ? 1 : 0);

    // s_out[0]   = outflow of the bucket preceding the current chunk (carry)
    // s_out[1+q] = outflow of local bucket q (0..127)
    __shared__ float s_out[CHUNK + 1];
    __shared__ bool  s_last;
    if (tid == 0) s_last = false;

    // ---- prologue: seed the carry for this block's first bucket ----
    {
        const int b0 = cbeg * CHUNK;
        float pe = 0.0f;
        if (b0 != 0 && tid < 4) {
            const int    bp = b0 - 1;
            const float  Hp = H[bp];
            const float4 sp = S4[(size_t)bp * 4 + tid];
            const float2 tp = T2[(size_t)bp * 4 + tid];
            pe = spigot_q(Hp, sp.x, sp.y, tp.x) + spigot_q(Hp, sp.z, sp.w, tp.y);
        }
        if (tid < 32) {
            pe += __shfl_xor_sync(0xffffffffu, pe, 1);
            pe += __shfl_xor_sync(0xffffffffu, pe, 2);
        }
        if (tid == 0) s_out[0] = (b0 == 0) ? __ldg(precip) : pe;
    }

    double acc = 0.0;   // last-layer partial (deterministic accumulation order)

    for (int c = cbeg; c < cend; ++c) {
        const int bA = c * CHUNK + quad;
        const int bB = bA + 64;

        // front-batched streaming loads (issue before any barrier)
        const float  HA = H[bA];
        const float  HB = H[bB];
        const float4 sA = __ldcs(&S4[(size_t)bA * 4 + ql]);
        const float4 sB = __ldcs(&S4[(size_t)bB * 4 + ql]);
        const float2 tA = __ldcs(&T2[(size_t)bA * 4 + ql]);
        const float2 tB = __ldcs(&T2[(size_t)bB * 4 + ql]);

        const float qA0 = spigot_q(HA, sA.x, sA.y, tA.x);
        const float qA1 = spigot_q(HA, sA.z, sA.w, tA.y);
        const float qB0 = spigot_q(HB, sB.x, sB.y, tB.x);
        const float qB1 = spigot_q(HB, sB.z, sB.w, tB.y);

        __stcs(&SQ2[(size_t)bA * 4 + ql], make_float2(qA0, qA1));
        __stcs(&SQ2[(size_t)bB * 4 + ql], make_float2(qB0, qB1));

        // bucket outflows: reduce over the 4 lanes of each quad
        float poA = qA0 + qA1;
        float poB = qB0 + qB1;
        poA += __shfl_xor_sync(0xffffffffu, poA, 1);
        poA += __shfl_xor_sync(0xffffffffu, poA, 2);
        poB += __shfl_xor_sync(0xffffffffu, poB, 1);
        poB += __shfl_xor_sync(0xffffffffu, poB, 2);

        __syncthreads();                       // prior iteration's s_out reads done
        if (ql == 0) { s_out[1 + quad] = poA; s_out[65 + quad] = poB; }
        __syncthreads();

        // H_new[b] = H[b] + outflow[b-1] - outflow[b]
        if (ql == 0) {
            __stcs(&Hn[bA], HA + s_out[quad] - poA);        // s_out[0] = carry
            __stcs(&Hn[bB], HB + s_out[64 + quad] - poB);
        }

        // last-layer accumulation (order fixed by tid & chunk order)
        if (c >= FIRST_LAST_CHUNK && tid < 32) {
            acc += (double)s_out[1 + tid]  + (double)s_out[33 + tid]
                 + (double)s_out[65 + tid] + (double)s_out[97 + tid];
        }

        // carry: only tid 0 reads s_out[0] (above), so this write is race-free
        if (tid == 0) s_out[0] = s_out[CHUNK];
    }

    // ---- per-block partial + deterministic global reduction ----
    if (tid < 32) {
        acc += __shfl_xor_sync(0xffffffffu, acc, 16);
        acc += __shfl_xor_sync(0xffffffffu, acc, 8);
        acc += __shfl_xor_sync(0xffffffffu, acc, 4);
        acc += __shfl_xor_sync(0xffffffffu, acc, 2);
        acc += __shfl_xor_sync(0xffffffffu, acc, 1);
        if (tid == 0) {
            g_partials[bid] = acc;
            __threadfence();
            unsigned t = atomicAdd(&g_count, 1u);
            if (t == GRID - 1) s_last = true;
        }
    }
    __syncthreads();

    if (s_last) {
        __threadfence();
        double a = 0.0;
        for (int i = tid; i < GRID; i += NTHREADS)   // fixed order -> deterministic
            a += g_partials[i];
        __shared__ double sm[NTHREADS];
        sm[tid] = a;
        __syncthreads();
        #pragma unroll
        for (int s = NTHREADS / 2; s > 0; s >>= 1) {
            if (tid < s) sm[tid] += sm[tid + s];
            __syncthreads();
        }
        if (tid == 0) {
            out[OUT_SCALAR] = (float)sm[0];
            g_count = 0;                              // reset for graph replay
        }
    }
}

extern "C" void kernel_launch(void* const* d_in, const int* in_sizes, int n_in,
                              void* d_out, int out_size) {
    const float*  H      = (const float*)d_in[0];
    const float4* S4     = (const float4*)d_in[1];
    const float2* T2     = (const float2*)d_in[2];
    const float*  precip = (const float*)d_in[3];

    nash_main<<<GRID, NTHREADS>>>(H, S4, T2, precip, (float*)d_out);
}

// round 9
// speedup vs baseline: 1.0758x; 1.0758x over previous
#include <cuda_runtime.h>

// NashCascadeNetwork: 8 layers x 524288 buckets, 8 spigots/bucket.
// Inputs (metadata order): H[NB] f32, S[NB,8,2] f32, theta[NB*8] f32, precip[1] f32
// Output (f32): [ H_new(NB) | s_q(NB*8) | network_outflow(1) ]
//
// One bucket per thread: 7 x 128-bit coalesced loads per thread, bucket
// outflow reduced in-register, b-1 coupling via shfl_up (+8 smem carries).

#define NB          4194304
#define NS          8
#define BPL         524288                   // buckets in last layer
#define BPB         256                      // buckets per block (1 per thread)
#define NTHREADS    256
#define NGRID       (NB / BPB)               // 16384
#define FIRST_LAST  ((NB - BPL) / BPB)       // 14336
#define NLASTBLK    (BPL / BPB)              // 2048
#define OUT_SQ_OFF  NB
#define OUT_SCALAR  (NB * (NS + 1))          // 37748736

__device__ double   g_partials[NLASTBLK];
__device__ unsigned g_count = 0;

// q = theta * sqrt(2*9.8*h) * 0.5*(tanh(h)+1) * area,  h = max(0, H - height)
// 0.5*(tanh(h)+1) == sigmoid(2h) == 1/(1+exp(-2h))  -> EX2 + RCP (err ~1e-7)
__device__ __forceinline__ float spigot_q(float Hb, float sh, float sa, float th) {
    float h = fmaxf(0.0f, Hb - sh);
    float e = __expf(-2.0f * h);
    float mod;
    asm("rcp.approx.f32 %0, %1;" : "=f"(mod) : "f"(1.0f + e));
    float s;
    asm("sqrt.approx.f32 %0, %1;" : "=f"(s) : "f"(19.6f * h));
    return th * s * mod * sa;
}

__global__ __launch_bounds__(NTHREADS)
void nash_main(const float* __restrict__ H,
               const float4* __restrict__ S4,     // [NB*4]
               const float4* __restrict__ T4,     // [NB*2]
               const float* __restrict__ precip,
               float* __restrict__ out)
{
    float*  Hn  = out;
    float4* SQ4 = (float4*)(out + OUT_SQ_OFF);

    const int tid  = threadIdx.x;
    const int lane = tid & 31;
    const int warp = tid >> 5;
    const int b    = blockIdx.x * BPB + tid;

    // ---- front-batched streaming loads: whole bucket in 7x128b + 1x32b ----
    const float  Hb = H[b];
    const float4 s0 = __ldcs(&S4[(size_t)b * 4 + 0]);
    const float4 s1 = __ldcs(&S4[(size_t)b * 4 + 1]);
    const float4 s2 = __ldcs(&S4[(size_t)b * 4 + 2]);
    const float4 s3 = __ldcs(&S4[(size_t)b * 4 + 3]);
    const float4 t0 = __ldcs(&T4[(size_t)b * 2 + 0]);
    const float4 t1 = __ldcs(&T4[(size_t)b * 2 + 1]);

    // ---- block-boundary bucket (b0-1): 8 lanes of warp 0, one spigot each ----
    float pe = 0.0f;
    if (warp == 0) {
        if (blockIdx.x != 0 && lane < 8) {
            const int    bp = blockIdx.x * BPB - 1;
            const float  Hp = H[bp];
            const float2 sp = ((const float2*)S4)[(size_t)bp * 8 + lane];
            const float  tp = ((const float*)T4)[(size_t)bp * 8 + lane];
            pe = spigot_q(Hp, sp.x, sp.y, tp);
        }
        pe += __shfl_xor_sync(0xffffffffu, pe, 1);
        pe += __shfl_xor_sync(0xffffffffu, pe, 2);
        pe += __shfl_xor_sync(0xffffffffu, pe, 4);   // lane 0 = full sum
    }

    // ---- 8 spigots, all in-register ----
    const float q0 = spigot_q(Hb, s0.x, s0.y, t0.x);
    const float q1 = spigot_q(Hb, s0.z, s0.w, t0.y);
    const float q2 = spigot_q(Hb, s1.x, s1.y, t0.z);
    const float q3 = spigot_q(Hb, s1.z, s1.w, t0.w);
    const float q4 = spigot_q(Hb, s2.x, s2.y, t1.x);
    const float q5 = spigot_q(Hb, s2.z, s2.w, t1.y);
    const float q6 = spigot_q(Hb, s3.x, s3.y, t1.z);
    const float q7 = spigot_q(Hb, s3.z, s3.w, t1.w);

    __stcs(&SQ4[(size_t)b * 2 + 0], make_float4(q0, q1, q2, q3));
    __stcs(&SQ4[(size_t)b * 2 + 1], make_float4(q4, q5, q6, q7));

    const float ob = ((q0 + q1) + (q2 + q3)) + ((q4 + q5) + (q6 + q7));

    // ---- inflow[b] = outflow[b-1]: shfl_up + 8 smem warp carries ----
    float inflow = __shfl_up_sync(0xffffffffu, ob, 1);
    __shared__ float s_carry[NTHREADS / 32];
    if (lane == 31) s_carry[warp] = ob;
    __syncthreads();
    if (lane == 0)
        inflow = (warp == 0)
               ? ((blockIdx.x == 0) ? __ldg(precip) : pe)
               : s_carry[warp - 1];
    __stcs(&Hn[b], Hb + inflow - ob);

    // ---- last-layer network-outflow reduction (fused, deterministic) ----
    if (blockIdx.x >= FIRST_LAST) {
        double a = (double)ob;
        a += __shfl_xor_sync(0xffffffffu, a, 16);
        a += __shfl_xor_sync(0xffffffffu, a, 8);
        a += __shfl_xor_sync(0xffffffffu, a, 4);
        a += __shfl_xor_sync(0xffffffffu, a, 2);
        a += __shfl_xor_sync(0xffffffffu, a, 1);

        __shared__ double sd[NTHREADS / 32];
        __shared__ bool   s_last;
        if (tid == 0) s_last = false;
        if (lane == 0) sd[warp] = a;
        __syncthreads();
        if (tid == 0) {
            double bs = ((sd[0] + sd[1]) + (sd[2] + sd[3]))
                      + ((sd[4] + sd[5]) + (sd[6] + sd[7]));
            g_partials[blockIdx.x - FIRST_LAST] = bs;
            __threadfence();
            unsigned t = atomicAdd(&g_count, 1u);
            if (t == NLASTBLK - 1) s_last = true;
        }
        __syncthreads();

        if (s_last) {
            // Last block alive: fixed-order reduction (deterministic).
            __threadfence();
            double acc = 0.0;
            #pragma unroll 4
            for (int i = tid; i < NLASTBLK; i += NTHREADS)
                acc += g_partials[i];
            __shared__ double sm[NTHREADS];
            sm[tid] = acc;
            __syncthreads();
            #pragma unroll
            for (int s = NTHREADS / 2; s > 0; s >>= 1) {
                if (tid < s) sm[tid] += sm[tid + s];
                __syncthreads();
            }
            if (tid == 0) {
                out[OUT_SCALAR] = (float)sm[0];
                g_count = 0;                     // reset for graph replay
            }
        }
    }
}

extern "C" void kernel_launch(void* const* d_in, const int* in_sizes, int n_in,
                              void* d_out, int out_size) {
    const float*  H      = (const float*)d_in[0];
    const float4* S4     = (const float4*)d_in[1];
    const float4* T4     = (const float4*)d_in[2];
    const float*  precip = (const float*)d_in[3];

    nash_main<<<NGRID, NTHREADS>>>(H, S4, T4, precip, (float*)d_out);
}